// round 7
// baseline (speedup 1.0000x reference)
#include <cuda_runtime.h>
#include <cuda_bf16.h>
#include <cstdint>

// Problem constants
#define BB   16
#define NN   2048
#define TT   168
#define DD   64
#define MM   2216            // N + T
#define TMR  64              // tile rows (A strip)
#define TNC  128             // tile cols (B strip)
#define NTJ  18
#define TILES_PER_B 341
#define TOTAL_TILES (TILES_PER_B * BB)   // 5456
#define NCTA 608             // 152 SMs * 4

// SMEM: A(hi+lo) 16KB resident; B(hi+lo) 32KB; Cs overlays B region (pitch 68)
#define AHI_OFF 0
#define ALO_OFF 8192
#define BHI_OFF 16384
#define BLO_OFF 32768
#define CS_PITCH 68
#define SMEM_BYTES (16384 + 128*CS_PITCH*4)   // 51200 -> 4 CTAs/SM

__device__ __forceinline__ uint32_t smem_u32(const void* p) {
    uint32_t a;
    asm("{ .reg .u64 t; cvta.to.shared.u64 t, %1; cvt.u32.u64 %0, t; }" : "=r"(a) : "l"(p));
    return a;
}

__device__ __forceinline__ float tanh_relu(float x) {
    x = fmaxf(x, 0.0f);
    float y;
    asm("tanh.approx.f32 %0, %1;" : "=f"(y) : "f"(x));
    return y;
}

__device__ __forceinline__ uint32_t sw128(uint32_t off) {
    return off ^ ((off >> 3) & 0x70);
}

__device__ __forceinline__ void split8(float4 v0, float4 v1, uint4& hp, uint4& lp) {
    __nv_bfloat162 h01 = __floats2bfloat162_rn(v0.x, v0.y);
    __nv_bfloat162 h23 = __floats2bfloat162_rn(v0.z, v0.w);
    __nv_bfloat162 h45 = __floats2bfloat162_rn(v1.x, v1.y);
    __nv_bfloat162 h67 = __floats2bfloat162_rn(v1.z, v1.w);
    __nv_bfloat162 l01 = __floats2bfloat162_rn(
        v0.x - __bfloat162float(__low2bfloat16(h01)),
        v0.y - __bfloat162float(__high2bfloat16(h01)));
    __nv_bfloat162 l23 = __floats2bfloat162_rn(
        v0.z - __bfloat162float(__low2bfloat16(h23)),
        v0.w - __bfloat162float(__high2bfloat16(h23)));
    __nv_bfloat162 l45 = __floats2bfloat162_rn(
        v1.x - __bfloat162float(__low2bfloat16(h45)),
        v1.y - __bfloat162float(__high2bfloat16(h45)));
    __nv_bfloat162 l67 = __floats2bfloat162_rn(
        v1.z - __bfloat162float(__low2bfloat16(h67)),
        v1.w - __bfloat162float(__high2bfloat16(h67)));
    hp.x = *(uint32_t*)&h01; hp.y = *(uint32_t*)&h23;
    hp.z = *(uint32_t*)&h45; hp.w = *(uint32_t*)&h67;
    lp.x = *(uint32_t*)&l01; lp.y = *(uint32_t*)&l23;
    lp.z = *(uint32_t*)&l45; lp.w = *(uint32_t*)&l67;
}

__device__ __forceinline__ void ldsm_x4(uint32_t addr, uint32_t& r0, uint32_t& r1,
                                        uint32_t& r2, uint32_t& r3) {
    asm volatile("ldmatrix.sync.aligned.m8n8.x4.shared.b16 {%0,%1,%2,%3}, [%4];"
                 : "=r"(r0), "=r"(r1), "=r"(r2), "=r"(r3) : "r"(addr));
}

__device__ __forceinline__ void mma16816(float* c, const uint32_t* a, const uint32_t* b) {
    asm volatile(
        "mma.sync.aligned.m16n8k16.row.col.f32.bf16.bf16.f32 "
        "{%0,%1,%2,%3}, {%4,%5,%6,%7}, {%8,%9}, {%0,%1,%2,%3};"
        : "+f"(c[0]), "+f"(c[1]), "+f"(c[2]), "+f"(c[3])
        : "r"(a[0]), "r"(a[1]), "r"(a[2]), "r"(a[3]), "r"(b[0]), "r"(b[1]));
}

__device__ __forceinline__ const float* row_ptr(const float* sp, const float* tp,
                                                int b, int g) {
    return (g < NN) ? sp + ((size_t)b * NN + g) * DD
                    : tp + ((size_t)b * TT + (g - NN)) * DD;
}

__device__ __forceinline__ void mirror_write(const float* Cs, float* out,
                                             int pB, int pRow0, int pCol0, int t) {
    #pragma unroll
    for (int it = 0; it < 16; ++it) {
        int u   = it * 128 + t;
        int lr4 = u & 15;
        int lc  = u >> 4;
        float4 v = *(const float4*)&Cs[lc * CS_PITCH + 4 * lr4];
        int gr_out = pCol0 + lc;
        int gc_out = pRow0 + 4 * lr4;
        if (gr_out < MM && gc_out + 3 < MM) {
            *(float4*)&out[((size_t)pB * MM + gr_out) * MM + gc_out] = v;
        } else if (gr_out < MM) {
            float* dst = &out[((size_t)pB * MM + gr_out) * MM + gc_out];
            if (gc_out     < MM) dst[0] = v.x;
            if (gc_out + 1 < MM) dst[1] = v.y;
            if (gc_out + 2 < MM) dst[2] = v.z;
            if (gc_out + 3 < MM) dst[3] = v.w;
        }
    }
}

__global__ __launch_bounds__(128, 4)
void stg_pers_kernel(const float* __restrict__ sp, const float* __restrict__ tp,
                     float* __restrict__ out)
{
    extern __shared__ char smem[];
    const uint32_t smem_base = smem_u32(smem);
    float* Cs = (float*)(smem + BHI_OFF);     // overlays B region

    const int t    = threadIdx.x;
    const int lane = t & 31;
    const int wid  = t >> 5;

    // chunk assignment: 592 CTAs x 9 tiles + 16 CTAs x 8 tiles = 5456
    const int id = blockIdx.x;
    int start, cnt;
    if (id < 592) { start = id * 9; cnt = 9; }
    else          { start = 5328 + (id - 592) * 8; cnt = 8; }

    const int m0w = (wid & 1) * 32;
    const int n0w = (wid >> 1) * 64;
    const int a_row  = m0w + (lane & 15);
    const int a_chk  = lane >> 4;
    const int b_rowb = n0w + ((lane >> 4) << 3) + (lane & 7);
    const int b_chk  = (lane >> 3) & 1;

    int cur_bi = -1;
    int pB = 0, pRow0 = 0, pCol0 = 0;
    bool have_prev = false;

    for (int tt = start; tt < start + cnt; ++tt) {
        // ---- decode tile (b, i, j) ----
        const int b = tt / TILES_PER_B;
        int p = tt - b * TILES_PER_B;
        int m = 0;
        while (m < 17 && p >= 2 * (NTJ - m)) { p -= 2 * (NTJ - m); ++m; }
        int i, j;
        if (m == 17) { i = 34; j = 17; }
        else {
            int c2 = NTJ - m;
            if (p >= c2) { i = 2 * m + 1; j = m + (p - c2); }
            else         { i = 2 * m;     j = m + p; }
        }
        const int row0 = i * TMR;
        const int col0 = j * TNC;
        const int abi  = b * 35 + i;
        const bool a_new = (abi != cur_bi);
        cur_bi = abi;

        // ---- prefetch B tile into registers (hidden under mirror epilogue) ----
        float4 bv0[8], bv1[8];
        #pragma unroll
        for (int it = 0; it < 8; ++it) {
            int idx = it * 128 + t;
            int rr  = idx >> 3;
            int c8  = idx & 7;
            int g   = col0 + rr;
            float4 v0 = make_float4(0.f,0.f,0.f,0.f), v1 = v0;
            if (g < MM) {
                const float* ptr = row_ptr(sp, tp, b, g);
                v0 = ((const float4*)ptr)[c8 * 2];
                v1 = ((const float4*)ptr)[c8 * 2 + 1];
            }
            bv0[it] = v0; bv1[it] = v1;
        }

        __syncthreads();                 // prev Cs STS visible
        if (have_prev)
            mirror_write(Cs, out, pB, pRow0, pCol0, t);
        __syncthreads();                 // Cs reads done; B region free

        // ---- convert + STS (A only when strip changes) ----
        if (a_new) {
            #pragma unroll
            for (int it = 0; it < 4; ++it) {
                int idx = it * 128 + t;
                int rr  = idx >> 3;
                int c8  = idx & 7;
                int g   = row0 + rr;
                float4 v0 = make_float4(0.f,0.f,0.f,0.f), v1 = v0;
                if (g < MM) {
                    const float* ptr = row_ptr(sp, tp, b, g);
                    v0 = ((const float4*)ptr)[c8 * 2];
                    v1 = ((const float4*)ptr)[c8 * 2 + 1];
                }
                uint4 hp, lp;
                split8(v0, v1, hp, lp);
                uint32_t sw = sw128((uint32_t)rr * 128 + (uint32_t)c8 * 16);
                *(uint4*)(smem + AHI_OFF + sw) = hp;
                *(uint4*)(smem + ALO_OFF + sw) = lp;
            }
        }
        #pragma unroll
        for (int it = 0; it < 8; ++it) {
            int idx = it * 128 + t;
            int rr  = idx >> 3;
            int c8  = idx & 7;
            uint4 hp, lp;
            split8(bv0[it], bv1[it], hp, lp);
            uint32_t sw = sw128((uint32_t)rr * 128 + (uint32_t)c8 * 16);
            *(uint4*)(smem + BHI_OFF + sw) = hp;
            *(uint4*)(smem + BLO_OFF + sw) = lp;
        }
        __syncthreads();                 // A/B ready

        // ---- MMA: 3-pass bf16 split ----
        float acc[2][8][4];
        #pragma unroll
        for (int mi = 0; mi < 2; ++mi)
            #pragma unroll
            for (int ni = 0; ni < 8; ++ni)
                #pragma unroll
                for (int q = 0; q < 4; ++q) acc[mi][ni][q] = 0.0f;

        #pragma unroll
        for (int pass = 0; pass < 3; ++pass) {
            const uint32_t abase = smem_base + (pass == 2 ? ALO_OFF : AHI_OFF);
            const uint32_t bbase = smem_base + (pass == 1 ? BLO_OFF : BHI_OFF);
            #pragma unroll
            for (int kk = 0; kk < 4; ++kk) {
                const int kc = kk * 2;
                uint32_t af[2][4];
                #pragma unroll
                for (int mi = 0; mi < 2; ++mi) {
                    uint32_t off = (uint32_t)(a_row + mi * 16) * 128 + (uint32_t)(kc + a_chk) * 16;
                    ldsm_x4(abase + sw128(off), af[mi][0], af[mi][1], af[mi][2], af[mi][3]);
                }
                uint32_t bf[8][2];
                #pragma unroll
                for (int bi = 0; bi < 4; ++bi) {
                    uint32_t off = (uint32_t)(b_rowb + bi * 16) * 128 + (uint32_t)(kc + b_chk) * 16;
                    ldsm_x4(bbase + sw128(off), bf[2*bi][0], bf[2*bi][1], bf[2*bi+1][0], bf[2*bi+1][1]);
                }
                #pragma unroll
                for (int mi = 0; mi < 2; ++mi)
                    #pragma unroll
                    for (int ni = 0; ni < 8; ++ni)
                        mma16816(acc[mi][ni], af[mi], bf[ni]);
            }
        }

        // ---- activation + direct write ----
        #pragma unroll
        for (int mi = 0; mi < 2; ++mi)
            #pragma unroll
            for (int ni = 0; ni < 8; ++ni)
                #pragma unroll
                for (int q = 0; q < 4; ++q)
                    acc[mi][ni][q] = tanh_relu(acc[mi][ni][q]);

        #pragma unroll
        for (int mi = 0; mi < 2; ++mi) {
            #pragma unroll
            for (int rh = 0; rh < 2; ++rh) {
                const int gr = row0 + m0w + mi * 16 + rh * 8 + (lane >> 2);
                if (gr >= MM) continue;
                const size_t rbase = ((size_t)b * MM + gr) * MM;
                #pragma unroll
                for (int ni = 0; ni < 8; ++ni) {
                    const int gc = col0 + n0w + ni * 8 + (lane & 3) * 2;
                    if (gc < MM) {
                        float2 v;
                        v.x = acc[mi][ni][rh * 2];
                        v.y = acc[mi][ni][rh * 2 + 1];
                        *(float2*)&out[rbase + gc] = v;
                    }
                }
            }
        }

        // ---- stage transposed tile into Cs (mirror happens next iteration) ----
        __syncthreads();                 // all warps done reading A/B (Cs overlays B)
        #pragma unroll
        for (int mi = 0; mi < 2; ++mi) {
            #pragma unroll
            for (int rh = 0; rh < 2; ++rh) {
                const int r = m0w + mi * 16 + rh * 8 + (lane >> 2);
                #pragma unroll
                for (int ni = 0; ni < 8; ++ni) {
                    const int c = n0w + ni * 8 + (lane & 3) * 2;
                    Cs[(c)     * CS_PITCH + r] = acc[mi][ni][rh * 2];
                    Cs[(c + 1) * CS_PITCH + r] = acc[mi][ni][rh * 2 + 1];
                }
            }
        }
        pB = b; pRow0 = row0; pCol0 = col0;
        have_prev = true;
    }

    // ---- drain: mirror of the last tile ----
    __syncthreads();
    if (have_prev)
        mirror_write(Cs, out, pB, pRow0, pCol0, t);
}

extern "C" void kernel_launch(void* const* d_in, const int* in_sizes, int n_in,
                              void* d_out, int out_size)
{
    const float* sp = (const float*)d_in[0];   // spatial  [16,2048,64] f32
    const float* tp = (const float*)d_in[1];   // temporal [16, 168,64] f32
    float* out = (float*)d_out;                // [16,2216,2216] f32

    cudaFuncSetAttribute(stg_pers_kernel, cudaFuncAttributeMaxDynamicSharedMemorySize, SMEM_BYTES);
    stg_pers_kernel<<<NCTA, 128, SMEM_BYTES>>>(sp, tp, out);
}

// round 8
// speedup vs baseline: 1.7916x; 1.7916x over previous
#include <cuda_runtime.h>
#include <cuda_bf16.h>
#include <cstdint>

// Problem constants
#define BB   16
#define NN   2048
#define TT   168
#define DD   64
#define MM   2216            // N + T
#define TMR  64              // tile rows (A strip)
#define TNC  128             // tile cols (B strip)
#define NTI  35              // ceil(MM/64)
#define NTJ  18              // ceil(MM/128)
#define TILES_PER_B 341      // sum over i of (18 - floor(i/2))

// SMEM: bf16 tiles, 128B rows, SW128-swizzled.
// A: 64 rows hi+lo = 16KB ; B: 128 rows hi+lo = 32KB. Total 48KB.
// After MMA, reused as Cs float[c:128][r: pitch 68].
#define AHI_OFF 0
#define ALO_OFF 8192
#define BHI_OFF 16384
#define BLO_OFF 32768
#define CS_PITCH 68
#define SMEM_BYTES 49152

__device__ __forceinline__ uint32_t smem_u32(const void* p) {
    uint32_t a;
    asm("{ .reg .u64 t; cvta.to.shared.u64 t, %1; cvt.u32.u64 %0, t; }" : "=r"(a) : "l"(p));
    return a;
}

__device__ __forceinline__ float tanh_relu(float x) {
    x = fmaxf(x, 0.0f);
    float y;
    asm("tanh.approx.f32 %0, %1;" : "=f"(y) : "f"(x));
    return y;
}

__device__ __forceinline__ uint32_t sw128(uint32_t off) {
    return off ^ ((off >> 3) & 0x70);
}

// streaming stores (evict-first): output is write-once
__device__ __forceinline__ void stcs_f2(float* p, float x, float y) {
    asm volatile("st.global.cs.v2.f32 [%0], {%1, %2};" :: "l"(p), "f"(x), "f"(y) : "memory");
}
__device__ __forceinline__ void stcs_f4(float* p, float4 v) {
    asm volatile("st.global.cs.v4.f32 [%0], {%1, %2, %3, %4};"
                 :: "l"(p), "f"(v.x), "f"(v.y), "f"(v.z), "f"(v.w) : "memory");
}
__device__ __forceinline__ void stcs_f1(float* p, float x) {
    asm volatile("st.global.cs.f32 [%0], %1;" :: "l"(p), "f"(x) : "memory");
}

// convert 8 floats -> 16B hi + 16B lo bf16 packs
__device__ __forceinline__ void split8(float4 v0, float4 v1, uint4& hp, uint4& lp) {
    __nv_bfloat162 h01 = __floats2bfloat162_rn(v0.x, v0.y);
    __nv_bfloat162 h23 = __floats2bfloat162_rn(v0.z, v0.w);
    __nv_bfloat162 h45 = __floats2bfloat162_rn(v1.x, v1.y);
    __nv_bfloat162 h67 = __floats2bfloat162_rn(v1.z, v1.w);
    __nv_bfloat162 l01 = __floats2bfloat162_rn(
        v0.x - __bfloat162float(__low2bfloat16(h01)),
        v0.y - __bfloat162float(__high2bfloat16(h01)));
    __nv_bfloat162 l23 = __floats2bfloat162_rn(
        v0.z - __bfloat162float(__low2bfloat16(h23)),
        v0.w - __bfloat162float(__high2bfloat16(h23)));
    __nv_bfloat162 l45 = __floats2bfloat162_rn(
        v1.x - __bfloat162float(__low2bfloat16(h45)),
        v1.y - __bfloat162float(__high2bfloat16(h45)));
    __nv_bfloat162 l67 = __floats2bfloat162_rn(
        v1.z - __bfloat162float(__low2bfloat16(h67)),
        v1.w - __bfloat162float(__high2bfloat16(h67)));
    hp.x = *(uint32_t*)&h01; hp.y = *(uint32_t*)&h23;
    hp.z = *(uint32_t*)&h45; hp.w = *(uint32_t*)&h67;
    lp.x = *(uint32_t*)&l01; lp.y = *(uint32_t*)&l23;
    lp.z = *(uint32_t*)&l45; lp.w = *(uint32_t*)&l67;
}

__device__ __forceinline__ void ldsm_x4(uint32_t addr, uint32_t& r0, uint32_t& r1,
                                        uint32_t& r2, uint32_t& r3) {
    asm volatile("ldmatrix.sync.aligned.m8n8.x4.shared.b16 {%0,%1,%2,%3}, [%4];"
                 : "=r"(r0), "=r"(r1), "=r"(r2), "=r"(r3) : "r"(addr));
}

__device__ __forceinline__ void mma16816(float* c, const uint32_t* a, const uint32_t* b) {
    asm volatile(
        "mma.sync.aligned.m16n8k16.row.col.f32.bf16.bf16.f32 "
        "{%0,%1,%2,%3}, {%4,%5,%6,%7}, {%8,%9}, {%0,%1,%2,%3};"
        : "+f"(c[0]), "+f"(c[1]), "+f"(c[2]), "+f"(c[3])
        : "r"(a[0]), "r"(a[1]), "r"(a[2]), "r"(a[3]), "r"(b[0]), "r"(b[1]));
}

__global__ __launch_bounds__(128, 4)
void stg_sym5_kernel(const float* __restrict__ sp, const float* __restrict__ tp,
                     float* __restrict__ out)
{
    extern __shared__ char smem[];
    const uint32_t smem_base = smem_u32(smem);

    const int t    = threadIdx.x;
    const int lane = t & 31;
    const int wid  = t >> 5;

    const int b = blockIdx.y;

    // map blockIdx.x -> (i strip of 64 rows, j strip of 128 cols), j >= floor(i/2)
    int p = blockIdx.x;
    int m = 0;
    while (m < 17 && p >= 2 * (NTJ - m)) { p -= 2 * (NTJ - m); ++m; }
    int i, j;
    if (m == 17) { i = 34; j = 17; }
    else {
        int cnt = NTJ - m;
        if (p >= cnt) { i = 2 * m + 1; j = m + (p - cnt); }
        else          { i = 2 * m;     j = m + p; }
    }
    const int row0 = i * TMR;
    const int col0 = j * TNC;

    // ---- load + split-convert A (64 rows) and B (128 rows) ----
    #pragma unroll
    for (int it = 0; it < 4; ++it) {
        int idx = it * 128 + t;
        int r   = idx >> 3;
        int c8  = idx & 7;
        int g   = row0 + r;
        float4 v0 = make_float4(0.f,0.f,0.f,0.f), v1 = v0;
        if (g < MM) {
            const float* ptr = (g < NN) ? sp + ((size_t)b * NN + g) * DD
                                        : tp + ((size_t)b * TT + (g - NN)) * DD;
            v0 = ((const float4*)ptr)[c8 * 2];
            v1 = ((const float4*)ptr)[c8 * 2 + 1];
        }
        uint4 hp, lp;
        split8(v0, v1, hp, lp);
        uint32_t sw = sw128((uint32_t)r * 128 + (uint32_t)c8 * 16);
        *(uint4*)(smem + AHI_OFF + sw) = hp;
        *(uint4*)(smem + ALO_OFF + sw) = lp;
    }
    #pragma unroll
    for (int it = 0; it < 8; ++it) {
        int idx = it * 128 + t;
        int r   = idx >> 3;
        int c8  = idx & 7;
        int g   = col0 + r;
        float4 v0 = make_float4(0.f,0.f,0.f,0.f), v1 = v0;
        if (g < MM) {
            const float* ptr = (g < NN) ? sp + ((size_t)b * NN + g) * DD
                                        : tp + ((size_t)b * TT + (g - NN)) * DD;
            v0 = ((const float4*)ptr)[c8 * 2];
            v1 = ((const float4*)ptr)[c8 * 2 + 1];
        }
        uint4 hp, lp;
        split8(v0, v1, hp, lp);
        uint32_t sw = sw128((uint32_t)r * 128 + (uint32_t)c8 * 16);
        *(uint4*)(smem + BHI_OFF + sw) = hp;
        *(uint4*)(smem + BLO_OFF + sw) = lp;
    }
    __syncthreads();

    // ---- warp tiles: 2 (m) x 2 (n) warps, each 32x64 ----
    const int m0w = (wid & 1) * 32;
    const int n0w = (wid >> 1) * 64;

    float acc[2][8][4];
    #pragma unroll
    for (int mi = 0; mi < 2; ++mi)
        #pragma unroll
        for (int ni = 0; ni < 8; ++ni)
            #pragma unroll
            for (int q = 0; q < 4; ++q) acc[mi][ni][q] = 0.0f;

    const int a_row  = m0w + (lane & 15);
    const int a_chk  = lane >> 4;
    const int b_rowb = n0w + ((lane >> 4) << 3) + (lane & 7);
    const int b_chk  = (lane >> 3) & 1;

    const uint32_t ahibase = smem_base + AHI_OFF;
    const uint32_t alobase = smem_base + ALO_OFF;
    const uint32_t bhibase = smem_base + BHI_OFF;
    const uint32_t blobase = smem_base + BLO_OFF;

    // kc-outer: per k-chunk load each fragment set once, run all 3 passes
    #pragma unroll
    for (int kk = 0; kk < 4; ++kk) {
        const int kc = kk * 2;
        uint32_t a_off[2], b_off[4];
        #pragma unroll
        for (int mi = 0; mi < 2; ++mi)
            a_off[mi] = sw128((uint32_t)(a_row + mi * 16) * 128 + (uint32_t)(kc + a_chk) * 16);
        #pragma unroll
        for (int bi = 0; bi < 4; ++bi)
            b_off[bi] = sw128((uint32_t)(b_rowb + bi * 16) * 128 + (uint32_t)(kc + b_chk) * 16);

        uint32_t af[2][4], bfh[8][2], bfl[8][2];
        #pragma unroll
        for (int bi = 0; bi < 4; ++bi)
            ldsm_x4(bhibase + b_off[bi], bfh[2*bi][0], bfh[2*bi][1], bfh[2*bi+1][0], bfh[2*bi+1][1]);
        #pragma unroll
        for (int mi = 0; mi < 2; ++mi)
            ldsm_x4(ahibase + a_off[mi], af[mi][0], af[mi][1], af[mi][2], af[mi][3]);
        #pragma unroll
        for (int mi = 0; mi < 2; ++mi)
            #pragma unroll
            for (int ni = 0; ni < 8; ++ni)
                mma16816(acc[mi][ni], af[mi], bfh[ni]);          // Ahi*Bhi
        #pragma unroll
        for (int bi = 0; bi < 4; ++bi)
            ldsm_x4(blobase + b_off[bi], bfl[2*bi][0], bfl[2*bi][1], bfl[2*bi+1][0], bfl[2*bi+1][1]);
        #pragma unroll
        for (int mi = 0; mi < 2; ++mi)
            #pragma unroll
            for (int ni = 0; ni < 8; ++ni)
                mma16816(acc[mi][ni], af[mi], bfl[ni]);          // Ahi*Blo
        #pragma unroll
        for (int mi = 0; mi < 2; ++mi)
            ldsm_x4(alobase + a_off[mi], af[mi][0], af[mi][1], af[mi][2], af[mi][3]);
        #pragma unroll
        for (int mi = 0; mi < 2; ++mi)
            #pragma unroll
            for (int ni = 0; ni < 8; ++ni)
                mma16816(acc[mi][ni], af[mi], bfh[ni]);          // Alo*Bhi
    }

    // ---- activation in place ----
    #pragma unroll
    for (int mi = 0; mi < 2; ++mi)
        #pragma unroll
        for (int ni = 0; ni < 8; ++ni)
            #pragma unroll
            for (int q = 0; q < 4; ++q)
                acc[mi][ni][q] = tanh_relu(acc[mi][ni][q]);

    // ---- direct write: out[row0+r][col0+c], coalesced streaming float2 ----
    #pragma unroll
    for (int mi = 0; mi < 2; ++mi) {
        #pragma unroll
        for (int rh = 0; rh < 2; ++rh) {
            const int gr = row0 + m0w + mi * 16 + rh * 8 + (lane >> 2);
            if (gr >= MM) continue;
            const size_t rbase = ((size_t)b * MM + gr) * MM;
            #pragma unroll
            for (int ni = 0; ni < 8; ++ni) {
                const int gc = col0 + n0w + ni * 8 + (lane & 3) * 2;
                if (gc < MM)
                    stcs_f2(&out[rbase + gc], acc[mi][ni][rh * 2], acc[mi][ni][rh * 2 + 1]);
            }
        }
    }

    // ---- mirror write via SMEM transpose ----
    __syncthreads();                   // done reading A/B tiles
    {
        float* Cs = (float*)smem;      // [c:128][r: pitch 68]
        #pragma unroll
        for (int mi = 0; mi < 2; ++mi) {
            #pragma unroll
            for (int rh = 0; rh < 2; ++rh) {
                const int r = m0w + mi * 16 + rh * 8 + (lane >> 2);
                #pragma unroll
                for (int ni = 0; ni < 8; ++ni) {
                    const int c = n0w + ni * 8 + (lane & 3) * 2;
                    Cs[(c)     * CS_PITCH + r] = acc[mi][ni][rh * 2];
                    Cs[(c + 1) * CS_PITCH + r] = acc[mi][ni][rh * 2 + 1];
                }
            }
        }
        __syncthreads();
        #pragma unroll
        for (int it = 0; it < 16; ++it) {
            int u   = it * 128 + t;
            int lr4 = u & 15;
            int lc  = u >> 4;
            float4 v = *(const float4*)&Cs[lc * CS_PITCH + 4 * lr4];
            int gr_out = col0 + lc;
            int gc_out = row0 + 4 * lr4;
            if (gr_out < MM && gc_out + 3 < MM) {
                stcs_f4(&out[((size_t)b * MM + gr_out) * MM + gc_out], v);
            } else if (gr_out < MM) {
                float* dst = &out[((size_t)b * MM + gr_out) * MM + gc_out];
                if (gc_out     < MM) stcs_f1(dst + 0, v.x);
                if (gc_out + 1 < MM) stcs_f1(dst + 1, v.y);
                if (gc_out + 2 < MM) stcs_f1(dst + 2, v.z);
                if (gc_out + 3 < MM) stcs_f1(dst + 3, v.w);
            }
        }
    }
}

extern "C" void kernel_launch(void* const* d_in, const int* in_sizes, int n_in,
                              void* d_out, int out_size)
{
    const float* sp = (const float*)d_in[0];   // spatial  [16,2048,64] f32
    const float* tp = (const float*)d_in[1];   // temporal [16, 168,64] f32
    float* out = (float*)d_out;                // [16,2216,2216] f32

    cudaFuncSetAttribute(stg_sym5_kernel, cudaFuncAttributeMaxDynamicSharedMemorySize, SMEM_BYTES);
    dim3 grid(TILES_PER_B, BB);
    stg_sym5_kernel<<<grid, 128, SMEM_BYTES>>>(sp, tp, out);
}